// round 6
// baseline (speedup 1.0000x reference)
#include <cuda_runtime.h>
#include <cstdint>

// ============================================================================
// OneHotEncoding via receiver-box candidate filtering (no index build).
//
// Output layout (float32):
//   [0, 4L)            input_tensor: per point (x, y, z, one_hot)
//   [4L, 4L+3B)        closest_points [B,3]
//   [4L+3B, 4L+4B)     min_index as float [B]
//
// K1 ub_kernel    : cooperative UB probe. 16 blocks x 8 receivers; each thread
//                   loads 8 contiguous sample points ONCE (6x LDG.128) and
//                   evaluates all 8 receivers from registers (R5 lesson: the
//                   old one-block-per-receiver probe was LDG-issue bound).
//                   Seeds g_best[r] with a VALID packed (d2<<32|idx) bound.
// K2 lists_kernel : 16^3 cell -> list of receivers whose [r-UB, r+UB]^3 box
//                   intersects the cell. Thread-per-cell, no atomics.
//                   Unconditionally correct: true NN lies within UB of r.
// K3 main_kernel  : stream pts once; write out[L,4]; for receivers listed in
//                   the point's cell, eval d2 + rare atomicMin packed u64.
//                   Last-finishing block finalizes (closest_points, min_index,
//                   one-hot scatter + reference's index-0 quirk).
//
// No global-atomic hot spots (R3 lesson). All device state re-seeded or
// self-reset every call => graph-replay deterministic.
// ============================================================================

#define GC         16
#define CELLS      (GC * GC * GC)        // 4096
#define MAXB       128
#define UB_BLOCKS  16
#define UB_THREADS 512
#define RPB        8                     // receivers per ub block
#define UBS        4096                  // sample points for the UB probe

__device__ unsigned long long g_best[MAXB];          // packed (d2bits<<32 | idx)
__device__ unsigned int       g_lcnt[CELLS];         // receivers per cell
__device__ unsigned char      g_list[CELLS * MAXB];  // receiver ids per cell
__device__ unsigned int       g_done;                // zero-init; self-resetting

__device__ __forceinline__ int cell_clamp(int c) {
    c = c < 0 ? 0 : c;
    return c > GC - 1 ? GC - 1 : c;
}
__device__ __forceinline__ int cell_of(float x) {
    return cell_clamp(__float2int_rd(x * (float)GC));
}

// ---------------------------------------------------------------------------
// K1: cooperative UB probe. Block b handles receivers [8b, 8b+8).
__global__ void __launch_bounds__(UB_THREADS)
ub_kernel(const float* __restrict__ pts, const float* __restrict__ recv,
          int L, int B)
{
    const int tid   = threadIdx.x;
    const int lane  = tid & 31;
    const int wid   = tid >> 5;
    const int rbase = blockIdx.x * RPB;

    // receivers for this block (registers)
    float rx[RPB], ry[RPB], rz[RPB];
#pragma unroll
    for (int r = 0; r < RPB; ++r) {
        int rb = rbase + r;
        rx[r] = (rb < B) ? recv[3 * rb + 0] : 0.f;
        ry[r] = (rb < B) ? recv[3 * rb + 1] : 0.f;
        rz[r] = (rb < B) ? recv[3 * rb + 2] : 0.f;
    }

    const int n  = (L < UBS) ? L : UBS;
    const int p0 = tid * 8;                       // this thread's 8 points

    float        bd[RPB];
    unsigned int bi[RPB];
#pragma unroll
    for (int r = 0; r < RPB; ++r) { bd[r] = 3.4e38f; bi[r] = 0u; }

    if (p0 < n) {
        float x[8], y[8], z[8];
        if (p0 + 8 <= n) {                        // fast path: 6x LDG.128
            const float4* src = reinterpret_cast<const float4*>(pts + 3 * p0);
            float4 v0 = src[0], v1 = src[1], v2 = src[2],
                   v3 = src[3], v4 = src[4], v5 = src[5];
            x[0]=v0.x; y[0]=v0.y; z[0]=v0.z;
            x[1]=v0.w; y[1]=v1.x; z[1]=v1.y;
            x[2]=v1.z; y[2]=v1.w; z[2]=v2.x;
            x[3]=v2.y; y[3]=v2.z; z[3]=v2.w;
            x[4]=v3.x; y[4]=v3.y; z[4]=v3.z;
            x[5]=v3.w; y[5]=v4.x; z[5]=v4.y;
            x[6]=v4.z; y[6]=v4.w; z[6]=v5.x;
            x[7]=v5.y; y[7]=v5.z; z[7]=v5.w;
        } else {
#pragma unroll
            for (int j = 0; j < 8; ++j) {
                int p = p0 + j;
                x[j] = (p < n) ? pts[3 * p + 0] : 1.0e30f;
                y[j] = (p < n) ? pts[3 * p + 1] : 1.0e30f;
                z[j] = (p < n) ? pts[3 * p + 2] : 1.0e30f;
            }
        }
#pragma unroll
        for (int r = 0; r < RPB; ++r) {
#pragma unroll
            for (int j = 0; j < 8; ++j) {
                float dx = x[j] - rx[r];
                float dy = y[j] - ry[r];
                float dz = z[j] - rz[r];
                float d2 = dx * dx + dy * dy + dz * dz;
                // strict <: earliest (ascending j => ascending index) wins
                if (d2 < bd[r]) { bd[r] = d2; bi[r] = (unsigned int)(p0 + j); }
            }
        }
    }

    // pack + warp shfl reduce + cross-warp smem reduce
    __shared__ unsigned long long s_b[UB_THREADS / 32][RPB];
#pragma unroll
    for (int r = 0; r < RPB; ++r) {
        unsigned long long pk =
            (((unsigned long long)__float_as_uint(bd[r])) << 32) |
            (unsigned long long)bi[r];
#pragma unroll
        for (int m = 16; m > 0; m >>= 1) {
            unsigned long long o = __shfl_xor_sync(0xffffffffu, pk, m);
            if (o < pk) pk = o;
        }
        if (lane == 0) s_b[wid][r] = pk;
    }
    __syncthreads();
    if (tid < RPB && (rbase + tid) < B) {
        unsigned long long bb = s_b[0][tid];
#pragma unroll
        for (int w = 1; w < UB_THREADS / 32; ++w)
            if (s_b[w][tid] < bb) bb = s_b[w][tid];
        g_best[rbase + tid] = bb;       // valid upper bound (actual point)
    }
}

// ---------------------------------------------------------------------------
// K2: thread-per-cell; build cell -> receiver candidate lists. No atomics.
__global__ void __launch_bounds__(512)
lists_kernel(const float* __restrict__ recv, int B)
{
    __shared__ int s_lx[MAXB], s_hx[MAXB], s_ly[MAXB], s_hy[MAXB],
                   s_lz[MAXB], s_hz[MAXB];
    const int tid = threadIdx.x;

    if (tid < B) {
        float ub2 = __uint_as_float((unsigned int)(g_best[tid] >> 32));
        float ub  = sqrtf(ub2) * 1.0001f + 1e-7f;   // ulp guard
        float rx = recv[3 * tid + 0];
        float ry = recv[3 * tid + 1];
        float rz = recv[3 * tid + 2];
        s_lx[tid] = cell_of(rx - ub);  s_hx[tid] = cell_of(rx + ub);
        s_ly[tid] = cell_of(ry - ub);  s_hy[tid] = cell_of(ry + ub);
        s_lz[tid] = cell_of(rz - ub);  s_hz[tid] = cell_of(rz + ub);
    }
    __syncthreads();

    const int cell = blockIdx.x * 512 + tid;        // 8 blocks x 512 = 4096
    if (cell >= CELLS) return;
    const int cx = cell & (GC - 1);
    const int cy = (cell >> 4) & (GC - 1);
    const int cz = cell >> 8;

    unsigned int n = 0;
    for (int r = 0; r < B; ++r) {
        bool hit = (cx >= s_lx[r]) & (cx <= s_hx[r]) &
                   (cy >= s_ly[r]) & (cy <= s_hy[r]) &
                   (cz >= s_lz[r]) & (cz <= s_hz[r]);
        if (hit) g_list[cell * MAXB + n++] = (unsigned char)r;
    }
    g_lcnt[cell] = n;
}

// ---------------------------------------------------------------------------
// K3: stream all points once; write out[L,4]; rare candidate evals + atomics.
//     Last-finishing block performs finalize.
__global__ void __launch_bounds__(512)
main_kernel(const float* __restrict__ pts, const float* __restrict__ recv,
            float* __restrict__ out, int L, int B)
{
    __shared__ float srx[MAXB], sry[MAXB], srz[MAXB];
    const int tid = threadIdx.x;
    if (tid < B) {
        srx[tid] = recv[3 * tid + 0];
        sry[tid] = recv[3 * tid + 1];
        srz[tid] = recv[3 * tid + 2];
    }
    __syncthreads();

    const int nGrp   = (L + 3) >> 2;                 // groups of 4 points
    const int gid    = blockIdx.x * 512 + tid;
    const int stride = gridDim.x * 512;

    for (int g = gid; g < nGrp; g += stride) {
        const int p0 = 4 * g;
        float x[4], y[4], z[4];
        if (p0 + 3 < L) {                            // fast path: 3x float4
            const float4* src = reinterpret_cast<const float4*>(pts + 3 * p0);
            float4 a = src[0], bq = src[1], c = src[2];
            x[0]=a.x;  y[0]=a.y;  z[0]=a.z;
            x[1]=a.w;  y[1]=bq.x; z[1]=bq.y;
            x[2]=bq.z; y[2]=bq.w; z[2]=c.x;
            x[3]=c.y;  y[3]=c.z;  z[3]=c.w;
        } else {
#pragma unroll
            for (int j = 0; j < 4; ++j) {
                int p = p0 + j;
                x[j] = (p < L) ? pts[3 * p + 0] : 2.0f;   // 2.0 -> never listed
                y[j] = (p < L) ? pts[3 * p + 1] : 2.0f;
                z[j] = (p < L) ? pts[3 * p + 2] : 2.0f;
            }
        }

#pragma unroll
        for (int j = 0; j < 4; ++j) {
            const int p = p0 + j;
            if (p >= L) break;
            *reinterpret_cast<float4*>(out + 4 * (size_t)p) =
                make_float4(x[j], y[j], z[j], 0.0f);

            int c = (cell_of(z[j]) * GC + cell_of(y[j])) * GC + cell_of(x[j]);
            unsigned int n = g_lcnt[c];
            for (unsigned int k = 0; k < n; ++k) {
                int r = g_list[c * MAXB + k];
                float dx = x[j] - srx[r];
                float dy = y[j] - sry[r];
                float dz = z[j] - srz[r];
                float d2 = dx * dx + dy * dy + dz * dz;
                unsigned long long pk =
                    (((unsigned long long)__float_as_uint(d2)) << 32) |
                    (unsigned long long)(unsigned int)p;
                // stale-high read is safe: atomicMin is authoritative
                if (pk < g_best[r]) atomicMin(&g_best[r], pk);
            }
        }
    }

    // ---- fused finalize: last-finishing block ----
    __threadfence();
    __syncthreads();
    __shared__ bool is_last;
    if (tid == 0) is_last = (atomicAdd(&g_done, 1u) == gridDim.x - 1);
    __syncthreads();
    if (!is_last) return;

    if (tid < B) {
        // authoritative L1-bypassing read: atomicMin with max operand
        unsigned long long bb = atomicMin(&g_best[tid], ~0ull);
        unsigned int idx = (unsigned int)(bb & 0xffffffffull);
        float* cp = out + 4 * (size_t)L;
        cp[3 * tid + 0] = pts[3 * idx + 0];
        cp[3 * tid + 1] = pts[3 * idx + 1];
        cp[3 * tid + 2] = pts[3 * idx + 2];
        out[4 * (size_t)L + 3 * B + tid] = (float)idx;   // min_index as float
        out[4 * (size_t)idx + 3] = 1.0f;                 // one-hot scatter
    }
    if (tid == 0) {
        if (B > 1) out[3] = 1.0f;       // reference quirk: index 0 also set
        g_done = 0u;                    // reset for next graph replay
    }
}

// ---------------------------------------------------------------------------
extern "C" void kernel_launch(void* const* d_in, const int* in_sizes, int n_in,
                              void* d_out, int out_size)
{
    const float* pts  = (const float*)d_in[0];   // mesh_3D flattened [L,3]
    const float* recv = (const float*)d_in[1];   // receiver_pos [B,3]
    float* out = (float*)d_out;

    int L = in_sizes[0] / 3;   // 1,000,000
    int B = in_sizes[1] / 3;   // 128

    ub_kernel   <<<(B + RPB - 1) / RPB, UB_THREADS>>>(pts, recv, L, B);
    lists_kernel<<<(CELLS + 511) / 512, 512>>>(recv, B);
    main_kernel <<<152, 512>>>(pts, recv, out, L, B);
}

// round 7
// speedup vs baseline: 1.0548x; 1.0548x over previous
#include <cuda_runtime.h>
#include <cstdint>

// ============================================================================
// OneHotEncoding — SINGLE fused kernel (R6 lesson: ~5us fixed cost per launch
// dominated the 3-kernel pipeline; fuse phases with software grid barriers).
//
// Output layout (float32):
//   [0, 4L)            input_tensor: per point (x, y, z, one_hot)
//   [4L, 4L+3B)        closest_points [B,3]
//   [4L+3B, 4L+4B)     min_index as float [B]
//
// Phase 1 (blocks 0..63) : cooperative UB probe, 2 receivers/block over 4096
//                          sample points (8 pts/thread via LDG.128). Writes a
//                          VALID packed (d2bits<<32|idx) bound to g_best[r]
//                          (plain store, exclusive owner; re-written every
//                          replay => no init needed).
// Phase 2 (blocks 0..7)  : 16^3 cell -> receiver candidate lists from the
//                          [r-UB, r+UB]^3 boxes. Unconditionally correct:
//                          the true NN lies within UB of r.
// Phase 3 (all blocks)   : stream pts once; write out[L,4]; for listed
//                          receivers eval d2 + rare atomicMin packed u64.
// Phase 4 (block 0)      : finalize closest_points / min_index / one-hot
//                          scatter + reference's index-0 quirk.
//
// Grid barriers: grid=152 <= SM count => all CTAs co-resident => spin-safe.
// g_gen grows monotonically across replays (harmless); g_arrive self-resets.
// ============================================================================

#define GC        16
#define CELLS     (GC * GC * GC)        // 4096
#define MAXB      128
#define GRID      152
#define THREADS   512
#define UB_BLOCKS 64
#define RPB       2                     // receivers per ub block
#define UBS       4096                  // sample points for the UB probe

__device__ unsigned long long g_best[MAXB];          // packed (d2bits<<32|idx)
__device__ unsigned int       g_lcnt[CELLS];         // receivers per cell
__device__ unsigned char      g_list[CELLS * MAXB];  // receiver ids per cell
__device__ unsigned int       g_arrive;              // barrier arrivals (self-reset)
__device__ unsigned int       g_gen;                 // barrier generation (monotone)

__device__ __forceinline__ int cell_clamp(int c) {
    c = c < 0 ? 0 : c;
    return c > GC - 1 ? GC - 1 : c;
}
__device__ __forceinline__ int cell_of(float x) {
    return cell_clamp(__float2int_rd(x * (float)GC));
}

// sense-reversing software grid barrier (all CTAs co-resident by construction)
__device__ __forceinline__ void grid_sync() {
    volatile unsigned int* vgen = &g_gen;
    __threadfence();                     // make this thread's work visible
    __syncthreads();
    if (threadIdx.x == 0) {
        unsigned int gen = *vgen;
        if (atomicAdd(&g_arrive, 1u) == GRID - 1) {
            g_arrive = 0;
            __threadfence();
            *vgen = gen + 1;             // release
        } else {
            while (*vgen == gen) { __nanosleep(32); }
        }
    }
    __syncthreads();
}

// ---------------------------------------------------------------------------
__global__ void __launch_bounds__(THREADS)
fused_kernel(const float* __restrict__ pts, const float* __restrict__ recv,
             float* __restrict__ out, int L, int B)
{
    const int tid  = threadIdx.x;
    const int lane = tid & 31;
    const int wid  = tid >> 5;
    const int bid  = blockIdx.x;

    __shared__ unsigned long long s_b[THREADS / 32][RPB];
    __shared__ int s_lx[MAXB], s_hx[MAXB], s_ly[MAXB], s_hy[MAXB],
                   s_lz[MAXB], s_hz[MAXB];
    __shared__ float srx[MAXB], sry[MAXB], srz[MAXB];

    // stage receivers once (used in phases 1 and 3)
    if (tid < B) {
        srx[tid] = recv[3 * tid + 0];
        sry[tid] = recv[3 * tid + 1];
        srz[tid] = recv[3 * tid + 2];
    }
    __syncthreads();

    // ======================= Phase 1: UB probe =======================
    if (bid < UB_BLOCKS) {
        const int rbase = bid * RPB;
        float rx[RPB], ry[RPB], rz[RPB];
#pragma unroll
        for (int r = 0; r < RPB; ++r) {
            int rb = rbase + r;
            rx[r] = (rb < B) ? srx[rb] : 0.f;
            ry[r] = (rb < B) ? sry[rb] : 0.f;
            rz[r] = (rb < B) ? srz[rb] : 0.f;
        }

        const int n  = (L < UBS) ? L : UBS;
        const int p0 = tid * 8;

        float        bd[RPB];
        unsigned int bi[RPB];
#pragma unroll
        for (int r = 0; r < RPB; ++r) { bd[r] = 3.4e38f; bi[r] = 0u; }

        if (p0 < n) {
            float x[8], y[8], z[8];
            if (p0 + 8 <= n) {                    // fast path: 6x LDG.128
                const float4* src = reinterpret_cast<const float4*>(pts + 3 * p0);
                float4 v0 = src[0], v1 = src[1], v2 = src[2],
                       v3 = src[3], v4 = src[4], v5 = src[5];
                x[0]=v0.x; y[0]=v0.y; z[0]=v0.z;
                x[1]=v0.w; y[1]=v1.x; z[1]=v1.y;
                x[2]=v1.z; y[2]=v1.w; z[2]=v2.x;
                x[3]=v2.y; y[3]=v2.z; z[3]=v2.w;
                x[4]=v3.x; y[4]=v3.y; z[4]=v3.z;
                x[5]=v3.w; y[5]=v4.x; z[5]=v4.y;
                x[6]=v4.z; y[6]=v4.w; z[6]=v5.x;
                x[7]=v5.y; y[7]=v5.z; z[7]=v5.w;
            } else {
#pragma unroll
                for (int j = 0; j < 8; ++j) {
                    int p = p0 + j;
                    x[j] = (p < n) ? pts[3 * p + 0] : 1.0e30f;
                    y[j] = (p < n) ? pts[3 * p + 1] : 1.0e30f;
                    z[j] = (p < n) ? pts[3 * p + 2] : 1.0e30f;
                }
            }
#pragma unroll
            for (int r = 0; r < RPB; ++r) {
#pragma unroll
                for (int j = 0; j < 8; ++j) {
                    float dx = x[j] - rx[r];
                    float dy = y[j] - ry[r];
                    float dz = z[j] - rz[r];
                    float d2 = dx * dx + dy * dy + dz * dz;
                    // strict <: earliest index wins within the thread
                    if (d2 < bd[r]) { bd[r] = d2; bi[r] = (unsigned int)(p0 + j); }
                }
            }
        }

#pragma unroll
        for (int r = 0; r < RPB; ++r) {
            unsigned long long pk =
                (((unsigned long long)__float_as_uint(bd[r])) << 32) |
                (unsigned long long)bi[r];
#pragma unroll
            for (int m = 16; m > 0; m >>= 1) {
                unsigned long long o = __shfl_xor_sync(0xffffffffu, pk, m);
                if (o < pk) pk = o;
            }
            if (lane == 0) s_b[wid][r] = pk;
        }
        __syncthreads();
        if (tid < RPB && (rbase + tid) < B) {
            unsigned long long bb = s_b[0][tid];
#pragma unroll
            for (int w = 1; w < THREADS / 32; ++w)
                if (s_b[w][tid] < bb) bb = s_b[w][tid];
            g_best[rbase + tid] = bb;    // plain store, exclusive owner
        }
    }

    grid_sync();   // g_best bounds visible to all

    // ======================= Phase 2: candidate lists =======================
    if (bid < CELLS / THREADS) {         // blocks 0..7
        if (tid < B) {
            volatile unsigned long long* vb = g_best;   // L1-bypassing read
            unsigned long long pk = vb[tid];
            float ub2 = __uint_as_float((unsigned int)(pk >> 32));
            float ub  = sqrtf(ub2) * 1.0001f + 1e-7f;   // ulp guard
            s_lx[tid] = cell_of(srx[tid] - ub);  s_hx[tid] = cell_of(srx[tid] + ub);
            s_ly[tid] = cell_of(sry[tid] - ub);  s_hy[tid] = cell_of(sry[tid] + ub);
            s_lz[tid] = cell_of(srz[tid] - ub);  s_hz[tid] = cell_of(srz[tid] + ub);
        }
        __syncthreads();

        const int cell = bid * THREADS + tid;
        const int cx = cell & (GC - 1);
        const int cy = (cell >> 4) & (GC - 1);
        const int cz = cell >> 8;

        unsigned int n = 0;
        for (int r = 0; r < B; ++r) {
            bool hit = (cx >= s_lx[r]) & (cx <= s_hx[r]) &
                       (cy >= s_ly[r]) & (cy <= s_hy[r]) &
                       (cz >= s_lz[r]) & (cz <= s_hz[r]);
            if (hit) g_list[cell * MAXB + n++] = (unsigned char)r;
        }
        g_lcnt[cell] = n;
    }

    grid_sync();   // lists visible to all

    // ======================= Phase 3: streaming pass =======================
    {
        const int nGrp   = (L + 3) >> 2;
        const int gid    = bid * THREADS + tid;
        const int stride = GRID * THREADS;

        for (int g = gid; g < nGrp; g += stride) {
            const int p0 = 4 * g;
            float x[4], y[4], z[4];
            if (p0 + 3 < L) {                        // fast path: 3x LDG.128
                const float4* src = reinterpret_cast<const float4*>(pts + 3 * p0);
                float4 a = src[0], bq = src[1], c = src[2];
                x[0]=a.x;  y[0]=a.y;  z[0]=a.z;
                x[1]=a.w;  y[1]=bq.x; z[1]=bq.y;
                x[2]=bq.z; y[2]=bq.w; z[2]=c.x;
                x[3]=c.y;  y[3]=c.z;  z[3]=c.w;
            } else {
#pragma unroll
                for (int j = 0; j < 4; ++j) {
                    int p = p0 + j;
                    x[j] = (p < L) ? pts[3 * p + 0] : 2.0f;  // 2.0 -> never listed
                    y[j] = (p < L) ? pts[3 * p + 1] : 2.0f;
                    z[j] = (p < L) ? pts[3 * p + 2] : 2.0f;
                }
            }

#pragma unroll
            for (int j = 0; j < 4; ++j) {
                const int p = p0 + j;
                if (p >= L) break;
                *reinterpret_cast<float4*>(out + 4 * (size_t)p) =
                    make_float4(x[j], y[j], z[j], 0.0f);

                int c = (cell_of(z[j]) * GC + cell_of(y[j])) * GC + cell_of(x[j]);
                unsigned int n = g_lcnt[c];
                for (unsigned int k = 0; k < n; ++k) {
                    int r = g_list[c * MAXB + k];
                    float dx = x[j] - srx[r];
                    float dy = y[j] - sry[r];
                    float dz = z[j] - srz[r];
                    float d2 = dx * dx + dy * dy + dz * dz;
                    unsigned long long pk =
                        (((unsigned long long)__float_as_uint(d2)) << 32) |
                        (unsigned long long)(unsigned int)p;
                    // stale-high read is safe (monotone decreasing; L1 flushed
                    // per launch); atomicMin is authoritative
                    if (pk < g_best[r]) atomicMin(&g_best[r], pk);
                }
            }
        }
    }

    grid_sync();   // all streaming stores + atomics complete

    // ======================= Phase 4: finalize (block 0) =======================
    if (bid == 0) {
        if (tid < B) {
            // authoritative L1-bypassing read
            unsigned long long bb = atomicMin(&g_best[tid], ~0ull);
            unsigned int idx = (unsigned int)(bb & 0xffffffffull);
            float* cp = out + 4 * (size_t)L;
            cp[3 * tid + 0] = pts[3 * idx + 0];
            cp[3 * tid + 1] = pts[3 * idx + 1];
            cp[3 * tid + 2] = pts[3 * idx + 2];
            out[4 * (size_t)L + 3 * B + tid] = (float)idx;  // min_index as float
            out[4 * (size_t)idx + 3] = 1.0f;                // one-hot scatter
        }
        if (tid == 0 && B > 1) out[3] = 1.0f;   // reference quirk: index 0 set
    }
}

// ---------------------------------------------------------------------------
extern "C" void kernel_launch(void* const* d_in, const int* in_sizes, int n_in,
                              void* d_out, int out_size)
{
    const float* pts  = (const float*)d_in[0];   // mesh_3D flattened [L,3]
    const float* recv = (const float*)d_in[1];   // receiver_pos [B,3]
    float* out = (float*)d_out;

    int L = in_sizes[0] / 3;   // 1,000,000
    int B = in_sizes[1] / 3;   // 128

    fused_kernel<<<GRID, THREADS>>>(pts, recv, out, L, B);
}

// round 8
// speedup vs baseline: 1.0676x; 1.0121x over previous
#include <cuda_runtime.h>
#include <cstdint>

// ============================================================================
// OneHotEncoding — single fused kernel, v2.
// R7 lessons applied: (a) 25% occupancy + dependent LDG chain made phase 3
// latency-bound => raise to 2 CTAs/SM (grid 304) and move the per-cell count
// table into smem (LDS replaces random dependent LDG); (b) 8 points/thread
// per iteration => all point loads front-batched (max MLP).
//
// Output layout (float32):
//   [0, 4L)            input_tensor: per point (x, y, z, one_hot)
//   [4L, 4L+3B)        closest_points [B,3]
//   [4L+3B, 4L+4B)     min_index as float [B]
//
// Phase 1 (blocks 0..63) : cooperative UB probe, 2 receivers/block over 4096
//                          sample points. Seeds g_best[r] with a VALID packed
//                          (d2bits<<32|idx) bound (plain store, exclusive).
// Phase 2 (blocks 0..7)  : 16^3 cell -> receiver candidate lists from the
//                          [r-UB, r+UB]^3 boxes (unconditionally covering).
// Phase 3 (all blocks)   : stream pts once; write out[L,4]; smem count table;
//                          rare candidate eval + packed u64 atomicMin.
// Phase 4 (block 0)      : finalize + one-hot scatter + index-0 quirk.
//
// Grid barrier: __launch_bounds__(512,2) guarantees 2 CTAs/SM co-residency
// (304 = 2 x 152 SMs). g_gen monotone across replays; g_arrive self-resets.
// ============================================================================

#define GC        16
#define CELLS     (GC * GC * GC)        // 4096
#define MAXB      128
#define GRID      304
#define THREADS   512
#define UB_BLOCKS 64
#define RPB       2                     // receivers per ub block
#define UBS       4096                  // sample points for the UB probe

__device__ unsigned long long g_best[MAXB];          // packed (d2bits<<32|idx)
__device__ unsigned char      g_lcnt[CELLS];         // receivers per cell (u8)
__device__ unsigned char      g_list[CELLS * MAXB];  // receiver ids per cell
__device__ unsigned int       g_arrive;              // barrier arrivals (self-reset)
__device__ unsigned int       g_gen;                 // barrier generation (monotone)

__device__ __forceinline__ int cell_clamp(int c) {
    c = c < 0 ? 0 : c;
    return c > GC - 1 ? GC - 1 : c;
}
__device__ __forceinline__ int cell_of(float x) {
    return cell_clamp(__float2int_rd(x * (float)GC));
}

// sense-reversing software grid barrier (co-residency by __launch_bounds__)
__device__ __forceinline__ void grid_sync() {
    volatile unsigned int* vgen = &g_gen;
    __threadfence();
    __syncthreads();
    if (threadIdx.x == 0) {
        unsigned int gen = *vgen;
        if (atomicAdd(&g_arrive, 1u) == GRID - 1) {
            g_arrive = 0;
            __threadfence();
            *vgen = gen + 1;             // release
        } else {
            while (*vgen == gen) { __nanosleep(32); }
        }
    }
    __syncthreads();
}

// ---------------------------------------------------------------------------
__global__ void __launch_bounds__(THREADS, 2)
fused_kernel(const float* __restrict__ pts, const float* __restrict__ recv,
             float* __restrict__ out, int L, int B)
{
    const int tid  = threadIdx.x;
    const int lane = tid & 31;
    const int wid  = tid >> 5;
    const int bid  = blockIdx.x;

    __shared__ unsigned long long s_b[THREADS / 32][RPB];
    __shared__ int s_lx[MAXB], s_hx[MAXB], s_ly[MAXB], s_hy[MAXB],
                   s_lz[MAXB], s_hz[MAXB];
    __shared__ float srx[MAXB], sry[MAXB], srz[MAXB];
    __shared__ unsigned char s_cnt[CELLS];           // 4 KB count table

    // stage receivers once (used in phases 1 and 3)
    if (tid < B) {
        srx[tid] = recv[3 * tid + 0];
        sry[tid] = recv[3 * tid + 1];
        srz[tid] = recv[3 * tid + 2];
    }
    __syncthreads();

    // ======================= Phase 1: UB probe =======================
    if (bid < UB_BLOCKS) {
        const int rbase = bid * RPB;
        float rx[RPB], ry[RPB], rz[RPB];
#pragma unroll
        for (int r = 0; r < RPB; ++r) {
            int rb = rbase + r;
            rx[r] = (rb < B) ? srx[rb] : 0.f;
            ry[r] = (rb < B) ? sry[rb] : 0.f;
            rz[r] = (rb < B) ? srz[rb] : 0.f;
        }

        const int n  = (L < UBS) ? L : UBS;
        const int p0 = tid * 8;

        float        bd[RPB];
        unsigned int bi[RPB];
#pragma unroll
        for (int r = 0; r < RPB; ++r) { bd[r] = 3.4e38f; bi[r] = 0u; }

        if (p0 < n) {
            float x[8], y[8], z[8];
            if (p0 + 8 <= n) {                    // fast path: 6x LDG.128
                const float4* src = reinterpret_cast<const float4*>(pts + 3 * p0);
                float4 v0 = src[0], v1 = src[1], v2 = src[2],
                       v3 = src[3], v4 = src[4], v5 = src[5];
                x[0]=v0.x; y[0]=v0.y; z[0]=v0.z;
                x[1]=v0.w; y[1]=v1.x; z[1]=v1.y;
                x[2]=v1.z; y[2]=v1.w; z[2]=v2.x;
                x[3]=v2.y; y[3]=v2.z; z[3]=v2.w;
                x[4]=v3.x; y[4]=v3.y; z[4]=v3.z;
                x[5]=v3.w; y[5]=v4.x; z[5]=v4.y;
                x[6]=v4.z; y[6]=v4.w; z[6]=v5.x;
                x[7]=v5.y; y[7]=v5.z; z[7]=v5.w;
            } else {
#pragma unroll
                for (int j = 0; j < 8; ++j) {
                    int p = p0 + j;
                    x[j] = (p < n) ? pts[3 * p + 0] : 1.0e30f;
                    y[j] = (p < n) ? pts[3 * p + 1] : 1.0e30f;
                    z[j] = (p < n) ? pts[3 * p + 2] : 1.0e30f;
                }
            }
#pragma unroll
            for (int r = 0; r < RPB; ++r) {
#pragma unroll
                for (int j = 0; j < 8; ++j) {
                    float dx = x[j] - rx[r];
                    float dy = y[j] - ry[r];
                    float dz = z[j] - rz[r];
                    float d2 = dx * dx + dy * dy + dz * dz;
                    if (d2 < bd[r]) { bd[r] = d2; bi[r] = (unsigned int)(p0 + j); }
                }
            }
        }

#pragma unroll
        for (int r = 0; r < RPB; ++r) {
            unsigned long long pk =
                (((unsigned long long)__float_as_uint(bd[r])) << 32) |
                (unsigned long long)bi[r];
#pragma unroll
            for (int m = 16; m > 0; m >>= 1) {
                unsigned long long o = __shfl_xor_sync(0xffffffffu, pk, m);
                if (o < pk) pk = o;
            }
            if (lane == 0) s_b[wid][r] = pk;
        }
        __syncthreads();
        if (tid < RPB && (rbase + tid) < B) {
            unsigned long long bb = s_b[0][tid];
#pragma unroll
            for (int w = 1; w < THREADS / 32; ++w)
                if (s_b[w][tid] < bb) bb = s_b[w][tid];
            g_best[rbase + tid] = bb;    // plain store, exclusive owner
        }
    }

    grid_sync();   // g_best bounds visible to all

    // ======================= Phase 2: candidate lists =======================
    if (bid < CELLS / THREADS) {         // blocks 0..7
        if (tid < B) {
            volatile unsigned long long* vb = g_best;   // L1-bypassing read
            unsigned long long pk = vb[tid];
            float ub2 = __uint_as_float((unsigned int)(pk >> 32));
            float ub  = sqrtf(ub2) * 1.0001f + 1e-7f;   // ulp guard
            s_lx[tid] = cell_of(srx[tid] - ub);  s_hx[tid] = cell_of(srx[tid] + ub);
            s_ly[tid] = cell_of(sry[tid] - ub);  s_hy[tid] = cell_of(sry[tid] + ub);
            s_lz[tid] = cell_of(srz[tid] - ub);  s_hz[tid] = cell_of(srz[tid] + ub);
        }
        __syncthreads();

        const int cell = bid * THREADS + tid;
        const int cx = cell & (GC - 1);
        const int cy = (cell >> 4) & (GC - 1);
        const int cz = cell >> 8;

        unsigned int n = 0;
        for (int r = 0; r < B; ++r) {
            bool hit = (cx >= s_lx[r]) & (cx <= s_hx[r]) &
                       (cy >= s_ly[r]) & (cy <= s_hy[r]) &
                       (cz >= s_lz[r]) & (cz <= s_hz[r]);
            if (hit) g_list[cell * MAXB + n++] = (unsigned char)r;
        }
        g_lcnt[cell] = (unsigned char)n;  // B <= 128 fits u8
    }

    grid_sync();   // lists visible to all

    // ---- copy count table to smem: LDS replaces dependent random LDG ----
    {
        const unsigned long long* src = reinterpret_cast<const unsigned long long*>(g_lcnt);
        unsigned long long* dst = reinterpret_cast<unsigned long long*>(s_cnt);
        if (tid < CELLS / 8) dst[tid] = src[tid];    // 512 threads x 8 B = 4 KB
    }
    __syncthreads();

    // ======================= Phase 3: streaming pass =======================
    {
        const int nGrp   = (L + 7) >> 3;             // groups of 8 points
        const int gid    = bid * THREADS + tid;
        const int stride = GRID * THREADS;

        for (int g = gid; g < nGrp; g += stride) {
            const int p0 = 8 * g;
            float x[8], y[8], z[8];
            if (p0 + 8 <= L) {                       // fast path: 6x LDG.128
                const float4* src = reinterpret_cast<const float4*>(pts + 3 * p0);
                float4 v0 = src[0], v1 = src[1], v2 = src[2],
                       v3 = src[3], v4 = src[4], v5 = src[5];
                x[0]=v0.x; y[0]=v0.y; z[0]=v0.z;
                x[1]=v0.w; y[1]=v1.x; z[1]=v1.y;
                x[2]=v1.z; y[2]=v1.w; z[2]=v2.x;
                x[3]=v2.y; y[3]=v2.z; z[3]=v2.w;
                x[4]=v3.x; y[4]=v3.y; z[4]=v3.z;
                x[5]=v3.w; y[5]=v4.x; z[5]=v4.y;
                x[6]=v4.z; y[6]=v4.w; z[6]=v5.x;
                x[7]=v5.y; y[7]=v5.z; z[7]=v5.w;
            } else {
#pragma unroll
                for (int j = 0; j < 8; ++j) {
                    int p = p0 + j;
                    x[j] = (p < L) ? pts[3 * p + 0] : 2.0f;  // 2.0 -> never listed
                    y[j] = (p < L) ? pts[3 * p + 1] : 2.0f;
                    z[j] = (p < L) ? pts[3 * p + 2] : 2.0f;
                }
            }

#pragma unroll
            for (int j = 0; j < 8; ++j) {
                const int p = p0 + j;
                if (p >= L) break;
                *reinterpret_cast<float4*>(out + 4 * (size_t)p) =
                    make_float4(x[j], y[j], z[j], 0.0f);

                int c = (cell_of(z[j]) * GC + cell_of(y[j])) * GC + cell_of(x[j]);
                unsigned int n = s_cnt[c];           // LDS, not LDG
                for (unsigned int k = 0; k < n; ++k) {
                    int r = g_list[c * MAXB + k];
                    float dx = x[j] - srx[r];
                    float dy = y[j] - sry[r];
                    float dz = z[j] - srz[r];
                    float d2 = dx * dx + dy * dy + dz * dz;
                    unsigned long long pk =
                        (((unsigned long long)__float_as_uint(d2)) << 32) |
                        (unsigned long long)(unsigned int)p;
                    // stale-high read safe (monotone decreasing within launch)
                    if (pk < g_best[r]) atomicMin(&g_best[r], pk);
                }
            }
        }
    }

    grid_sync();   // all streaming stores + atomics complete

    // ======================= Phase 4: finalize (block 0) =======================
    if (bid == 0) {
        if (tid < B) {
            // authoritative L1-bypassing read
            unsigned long long bb = atomicMin(&g_best[tid], ~0ull);
            unsigned int idx = (unsigned int)(bb & 0xffffffffull);
            float* cp = out + 4 * (size_t)L;
            cp[3 * tid + 0] = pts[3 * idx + 0];
            cp[3 * tid + 1] = pts[3 * idx + 1];
            cp[3 * tid + 2] = pts[3 * idx + 2];
            out[4 * (size_t)L + 3 * B + tid] = (float)idx;  // min_index as float
            out[4 * (size_t)idx + 3] = 1.0f;                // one-hot scatter
        }
        if (tid == 0 && B > 1) out[3] = 1.0f;   // reference quirk: index 0 set
    }
}

// ---------------------------------------------------------------------------
extern "C" void kernel_launch(void* const* d_in, const int* in_sizes, int n_in,
                              void* d_out, int out_size)
{
    const float* pts  = (const float*)d_in[0];   // mesh_3D flattened [L,3]
    const float* recv = (const float*)d_in[1];   // receiver_pos [B,3]
    float* out = (float*)d_out;

    int L = in_sizes[0] / 3;   // 1,000,000
    int B = in_sizes[1] / 3;   // 128

    fused_kernel<<<GRID, THREADS>>>(pts, recv, out, L, B);
}